// round 6
// baseline (speedup 1.0000x reference)
#include <cuda_runtime.h>
#include <cuda_bf16.h>

// ---------------------------------------------------------------------------
// Raymarcher: B=1, H=W=512, G=128, 64 steps, dt=0.02.
//
// Correctness: the JAX/XLA-GPU reference lowers fp32 division approximately;
// floor(tmin/dt) behaves as floor(tmin * 50.0f) (fl(1/0.02f) == 50.0f), which
// flips the floored step index for k in {5,10,13} vs correctly-rounded
// division. We must reproduce the reference's arithmetic: t0 via multiply by
// 50.0f. Position updates and the alpha/contrib chain stay in exact
// __fadd_rn/__fmul_rn order (they gate discontinuous decisions: inside test,
// saturation). Continuous interpolation math may use FMA freely (value-
// continuous across any cell flip -> ~1e-6 level noise only).
//
// Perf: repack warp[3,G^3] / template[4,G^3] into channel-interleaved float4
// grids in __device__ scratch (one corner = one 16B load = one L2 sector).
// Packed volumes (67 MB) stay resident in the 126 MB L2. One thread per ray,
// dead-ray (exited cube / alpha==1) skip + warp-uniform break.
// ---------------------------------------------------------------------------

static constexpr int GDIM = 128;
static constexpr int G3   = GDIM * GDIM * GDIM;

__device__ float4 g_warp[G3];   // (x,y,z, pad)
__device__ float4 g_tmpl[G3];   // (r,g,b, density)

__global__ void __launch_bounds__(256)
repack_kernel(const float* __restrict__ w, const float* __restrict__ t)
{
    int i = blockIdx.x * 256 + threadIdx.x;
    if (i < G3) {
        g_warp[i] = make_float4(w[i], w[i + G3], w[i + 2 * G3], 0.0f);
        g_tmpl[i] = make_float4(t[i], t[i + G3], t[i + 2 * G3], t[i + 3 * G3]);
    }
}

// Trilinear sample of an interleaved float4 volume (grid_sample 3D,
// align_corners=True, zeros padding). pts in [-1,1]:
//   x = ((p + 1) * 0.5) * 127; corner weight ((zw*yw)*xw), zeroed per-axis
//   when that plane is out of bounds; indices clamped.
__device__ __forceinline__ float4 tri4(const float4* __restrict__ vol,
                                       float px, float py, float pz)
{
    float x = __fmul_rn(__fmul_rn(__fadd_rn(px, 1.0f), 0.5f), 127.0f);
    float y = __fmul_rn(__fmul_rn(__fadd_rn(py, 1.0f), 0.5f), 127.0f);
    float z = __fmul_rn(__fmul_rn(__fadd_rn(pz, 1.0f), 0.5f), 127.0f);

    float xf = floorf(x), yf = floorf(y), zf = floorf(z);
    float wx = x - xf, wy = y - yf, wz = z - zf;
    int x0 = (int)xf, y0 = (int)yf, z0 = (int)zf;
    int x1 = x0 + 1,  y1 = y0 + 1,  z1 = z0 + 1;

    // per-axis weights, zeroed when that plane is out of bounds
    float ux0 = ((unsigned)x0 < (unsigned)GDIM) ? (1.0f - wx) : 0.0f;
    float ux1 = ((unsigned)x1 < (unsigned)GDIM) ? wx          : 0.0f;
    float uy0 = ((unsigned)y0 < (unsigned)GDIM) ? (1.0f - wy) : 0.0f;
    float uy1 = ((unsigned)y1 < (unsigned)GDIM) ? wy          : 0.0f;
    float uz0 = ((unsigned)z0 < (unsigned)GDIM) ? (1.0f - wz) : 0.0f;
    float uz1 = ((unsigned)z1 < (unsigned)GDIM) ? wz          : 0.0f;

    int xc0 = min(max(x0, 0), GDIM - 1);
    int xc1 = min(max(x1, 0), GDIM - 1);
    int yc0 = min(max(y0, 0), GDIM - 1);
    int yc1 = min(max(y1, 0), GDIM - 1);
    int zc0 = min(max(z0, 0), GDIM - 1);
    int zc1 = min(max(z1, 0), GDIM - 1);

    int r00 = (zc0 * GDIM + yc0) * GDIM;
    int r01 = (zc0 * GDIM + yc1) * GDIM;
    int r10 = (zc1 * GDIM + yc0) * GDIM;
    int r11 = (zc1 * GDIM + yc1) * GDIM;

    float w00 = uz0 * uy0;
    float w01 = uz0 * uy1;
    float w10 = uz1 * uy0;
    float w11 = uz1 * uy1;

    float4 acc = make_float4(0.0f, 0.0f, 0.0f, 0.0f);
#define TRI_ACC(IDX, WGT)                                         \
    do {                                                          \
        float4 v_ = __ldg(&vol[(IDX)]);                           \
        float  W_ = (WGT);                                        \
        acc.x = fmaf(v_.x, W_, acc.x);                            \
        acc.y = fmaf(v_.y, W_, acc.y);                            \
        acc.z = fmaf(v_.z, W_, acc.z);                            \
        acc.w = fmaf(v_.w, W_, acc.w);                            \
    } while (0)

    // x0/x1 pairs adjacent in memory -> second load of each pair is an L1 hit
    TRI_ACC(r00 + xc0, w00 * ux0);
    TRI_ACC(r00 + xc1, w00 * ux1);
    TRI_ACC(r01 + xc0, w01 * ux0);
    TRI_ACC(r01 + xc1, w01 * ux1);
    TRI_ACC(r10 + xc0, w10 * ux0);
    TRI_ACC(r10 + xc1, w10 * ux1);
    TRI_ACC(r11 + xc0, w11 * ux0);
    TRI_ACC(r11 + xc1, w11 * ux1);
#undef TRI_ACC
    return acc;
}

__global__ void __launch_bounds__(256)
raymarch_kernel(const float* __restrict__ raypos,
                const float* __restrict__ raydir,
                const float* __restrict__ tminmax,
                const int*   __restrict__ nsteps_p,
                float* __restrict__ out, int N)
{
    int n = blockIdx.x * 256 + threadIdx.x;
    if (n >= N) return;

    const float dtf = 0.02f;  // DT / VOLRADIUS as float32

    float dx = raydir[3 * n + 0];
    float dy = raydir[3 * n + 1];
    float dz = raydir[3 * n + 2];

    // t0 = floor(tmin / dt) * dt, with the division performed as the XLA-GPU
    // reference does: multiply by the f32 reciprocal, fl(1/0.02f) == 50.0f.
    // (Correctly-rounded division flips floor() for k in {5,10,13}.)
    float q  = floorf(__fmul_rn(tminmax[2 * n], 50.0f));
    float t0 = __fmul_rn(q, dtf);

    // pos = raypos + rdir*t0: rounded mul, then rounded add (no FMA) — must
    // bit-match the reference so the discontinuous inside test agrees.
    float px = __fadd_rn(raypos[3 * n + 0], __fmul_rn(dx, t0));
    float py = __fadd_rn(raypos[3 * n + 1], __fmul_rn(dy, t0));
    float pz = __fadd_rn(raypos[3 * n + 2], __fmul_rn(dz, t0));

    // Per-step increment: same rounded constant every step (reference's
    // pos + rdir*dt). Each axis trajectory is monotone in fp, so once a ray
    // leaves the open cube it never re-enters -> exact skip.
    float cx = __fmul_rn(dx, dtf);
    float cy = __fmul_rn(dy, dtf);
    float cz = __fmul_rn(dz, dtf);

    float r = 0.0f, g = 0.0f, b = 0.0f, a = 0.0f;
    int ns = nsteps_p ? nsteps_p[0] : 64;

    for (int s = 0; s < ns; ++s) {
        bool inside = (px > -1.0f) && (px < 1.0f) &&
                      (py > -1.0f) && (py < 1.0f) &&
                      (pz > -1.0f) && (pz < 1.0f);
        // Outside -> contrib exactly 0 forever (monotone trajectories).
        // alpha saturates to exactly 1.0 (Sterbenz) -> contrib exactly 0.
        bool done = (!inside) || (a >= 1.0f);
        unsigned m = __activemask();
        if (__all_sync(m, done)) break;

        if (!done) {
            float4 sp = tri4(g_warp, px, py, pz);          // warped coords
            float4 v  = tri4(g_tmpl, sp.x, sp.y, sp.z);    // rgb + density
            // contrib = min(a + v.w*dt, 1) - a, reference rounding order
            // (exact ops: gates the permanent saturation skip).
            float av = __fadd_rn(a, __fmul_rn(v.w, dtf));
            float contrib = __fadd_rn(fminf(av, 1.0f), -a);
            r = __fadd_rn(r, __fmul_rn(v.x, contrib));
            g = __fadd_rn(g, __fmul_rn(v.y, contrib));
            b = __fadd_rn(b, __fmul_rn(v.z, contrib));
            a = __fadd_rn(a, contrib);
        }
        px = __fadd_rn(px, cx);
        py = __fadd_rn(py, cy);
        pz = __fadd_rn(pz, cz);
    }

    // output layout [1, 4, H, W] -> channel-major planes of N
    out[0 * N + n] = r;
    out[1 * N + n] = g;
    out[2 * N + n] = b;
    out[3 * N + n] = a;
}

extern "C" void kernel_launch(void* const* d_in, const int* in_sizes, int n_in,
                              void* d_out, int out_size)
{
    const float* raypos = (const float*)d_in[0];
    const float* raydir = (const float*)d_in[1];
    const float* tmm    = (const float*)d_in[2];
    const float* warp   = (const float*)d_in[3];
    const float* tmpl   = (const float*)d_in[4];
    const int*   nsteps = (n_in > 5) ? (const int*)d_in[5] : nullptr;

    int N = in_sizes[0] / 3;  // number of rays (B*H*W)

    repack_kernel<<<(G3 + 255) / 256, 256>>>(warp, tmpl);
    raymarch_kernel<<<(N + 255) / 256, 256>>>(raypos, raydir, tmm, nsteps,
                                              (float*)d_out, N);
}

// round 7
// speedup vs baseline: 1.1415x; 1.1415x over previous
#include <cuda_runtime.h>
#include <cuda_fp16.h>

// ---------------------------------------------------------------------------
// Raymarcher: B=1, H=W=512, G=128, 64 steps, dt=0.02.
//
// R6 ncu: L1TEX 86% = binding (16 scattered LDG.128 per step per lane).
// This version halves the scattered-access count: both volumes are repacked
// into overlapping x-pair entries of 16B, so ONE LDG.128 fetches both x
// corners:
//   warp  entry[x] = snorm16 {x,y,z}[x], {x,y,z}[x+1]  (12B used of 16B)
//   tmpl  entry[x] = unorm16 {r,g,b,d}[x], {r,g,b,d}[x+1] (16B)
// -> 4 loads per trilinear sample, 8 per step (was 16). Quantization error:
// template unorm16 ~1e-5 (negligible); warp snorm16 shifts template coords by
// ~1e-3 voxel -> ~3e-4 output rel err (system is non-chaotic, R4-verified).
// Packed volumes 67 MB stay L2-resident.
//
// Discontinuity gates preserved bit-exactly vs the XLA reference:
//   t0 = floor(tmin * 50.0f) * 0.02f   (XLA lowers the division as rcp-mul)
//   position updates via __fadd_rn/__fmul_rn (no FMA) -> inside test matches
// All sampling boundary handling is continuous (clamped cell index + natural
// weights reproduce grid_sample zeros padding at every reachable coord).
// ---------------------------------------------------------------------------

static constexpr int GDIM = 128;
static constexpr int G3   = GDIM * GDIM * GDIM;

__device__ int4 g_warpP[G3];   // snorm16 pairs: (x0,y0),(z0,x1),(y1,z1),pad
__device__ int4 g_tmplP[G3];   // unorm16 pairs: (r0,g0),(b0,d0),(r1,g1),(b1,d1)

__device__ __forceinline__ int pack2(int lo, int hi) {
    return (lo & 0xffff) | (hi << 16);
}
__device__ __forceinline__ int qs(float v) {       // snorm16
    return (int)rintf(v * 32767.0f);
}
__device__ __forceinline__ int qu(float v) {       // unorm16
    return (int)rintf(v * 65535.0f);
}
__device__ __forceinline__ float s16lo(int v) { return (float)(short)(v & 0xffff); }
__device__ __forceinline__ float s16hi(int v) { return (float)(short)(v >> 16); }
__device__ __forceinline__ float u16lo(int v) { return (float)(v & 0xffff); }
__device__ __forceinline__ float u16hi(int v) { return (float)((unsigned)v >> 16); }

__global__ void __launch_bounds__(256)
repack_kernel(const float* __restrict__ w, const float* __restrict__ t)
{
    int i = blockIdx.x * 256 + threadIdx.x;
    if (i >= G3) return;
    int x = i & (GDIM - 1);
    int j = (x < GDIM - 1) ? i + 1 : i;   // entry[127] slot1 is never used

    int4 e;
    e.x = pack2(qs(w[i]),          qs(w[i + G3]));
    e.y = pack2(qs(w[i + 2 * G3]), qs(w[j]));
    e.z = pack2(qs(w[j + G3]),     qs(w[j + 2 * G3]));
    e.w = 0;
    g_warpP[i] = e;

    int4 f;
    f.x = pack2(qu(t[i]),          qu(t[i + G3]));
    f.y = pack2(qu(t[i + 2 * G3]), qu(t[i + 3 * G3]));
    f.z = pack2(qu(t[j]),          qu(t[j + G3]));
    f.w = pack2(qu(t[j + 2 * G3]), qu(t[j + 3 * G3]));
    g_tmplP[i] = f;
}

// Cell + weights for one axis: clamp the CELL to [0,126] and let the
// fractional weight absorb the boundary (wx==1 at u==127 selects vox[127]
// with weight 1 — identical to grid_sample align_corners=True zeros padding
// for every coordinate reachable here, with no OOB addressing).
__device__ __forceinline__ void cellw(float p, int& c, float& wf)
{
    float u  = (p + 1.0f) * 63.5f;
    float uf = fminf(fmaxf(floorf(u), 0.0f), 126.0f);
    wf = u - uf;
    c  = (int)uf;
}

// warp sample: 4 x LDG.128, snorm16 pairs -> (sx,sy,sz) scaled to [-1,1]
__device__ __forceinline__ void sampleWarp(float px, float py, float pz,
                                           float& ox, float& oy, float& oz)
{
    int x0, y0, z0; float wx, wy, wz;
    cellw(px, x0, wx); cellw(py, y0, wy); cellw(pz, z0, wz);

    int base = (z0 * GDIM + y0) * GDIM + x0;
    int4 e00 = __ldg(&g_warpP[base]);
    int4 e01 = __ldg(&g_warpP[base + GDIM]);
    int4 e10 = __ldg(&g_warpP[base + GDIM * GDIM]);
    int4 e11 = __ldg(&g_warpP[base + GDIM * GDIM + GDIM]);

    float vy = 1.0f - wy, vz = 1.0f - wz, vx = 1.0f - wx;
    float a00 = vz * vy, a01 = vz * wy, a10 = wz * vy, a11 = wz * wy;

    float sx, sy, sz;
    {   float c0 = a00 * vx, c1 = a00 * wx;
        sx =      s16lo(e00.x) * c0; sy =      s16hi(e00.x) * c0; sz =      s16lo(e00.y) * c0;
        sx = fmaf(s16hi(e00.y),  c1, sx); sy = fmaf(s16lo(e00.z), c1, sy); sz = fmaf(s16hi(e00.z), c1, sz); }
    {   float c0 = a01 * vx, c1 = a01 * wx;
        sx = fmaf(s16lo(e01.x), c0, sx); sy = fmaf(s16hi(e01.x), c0, sy); sz = fmaf(s16lo(e01.y), c0, sz);
        sx = fmaf(s16hi(e01.y), c1, sx); sy = fmaf(s16lo(e01.z), c1, sy); sz = fmaf(s16hi(e01.z), c1, sz); }
    {   float c0 = a10 * vx, c1 = a10 * wx;
        sx = fmaf(s16lo(e10.x), c0, sx); sy = fmaf(s16hi(e10.x), c0, sy); sz = fmaf(s16lo(e10.y), c0, sz);
        sx = fmaf(s16hi(e10.y), c1, sx); sy = fmaf(s16lo(e10.z), c1, sy); sz = fmaf(s16hi(e10.z), c1, sz); }
    {   float c0 = a11 * vx, c1 = a11 * wx;
        sx = fmaf(s16lo(e11.x), c0, sx); sy = fmaf(s16hi(e11.x), c0, sy); sz = fmaf(s16lo(e11.y), c0, sz);
        sx = fmaf(s16hi(e11.y), c1, sx); sy = fmaf(s16lo(e11.z), c1, sy); sz = fmaf(s16hi(e11.z), c1, sz); }

    const float s = 1.0f / 32767.0f;
    ox = sx * s; oy = sy * s; oz = sz * s;
}

// template sample: 4 x LDG.128, unorm16 pairs -> (r,g,b,d) scaled to [0,1]
__device__ __forceinline__ void sampleTmpl(float px, float py, float pz,
                                           float& r, float& g, float& b, float& d)
{
    int x0, y0, z0; float wx, wy, wz;
    cellw(px, x0, wx); cellw(py, y0, wy); cellw(pz, z0, wz);

    int base = (z0 * GDIM + y0) * GDIM + x0;
    int4 e00 = __ldg(&g_tmplP[base]);
    int4 e01 = __ldg(&g_tmplP[base + GDIM]);
    int4 e10 = __ldg(&g_tmplP[base + GDIM * GDIM]);
    int4 e11 = __ldg(&g_tmplP[base + GDIM * GDIM + GDIM]);

    float vy = 1.0f - wy, vz = 1.0f - wz, vx = 1.0f - wx;
    float a00 = vz * vy, a01 = vz * wy, a10 = wz * vy, a11 = wz * wy;

    float sr, sg, sb, sd;
    {   float c0 = a00 * vx, c1 = a00 * wx;
        sr =      u16lo(e00.x) * c0; sg =      u16hi(e00.x) * c0;
        sb =      u16lo(e00.y) * c0; sd =      u16hi(e00.y) * c0;
        sr = fmaf(u16lo(e00.z), c1, sr); sg = fmaf(u16hi(e00.z), c1, sg);
        sb = fmaf(u16lo(e00.w), c1, sb); sd = fmaf(u16hi(e00.w), c1, sd); }
    {   float c0 = a01 * vx, c1 = a01 * wx;
        sr = fmaf(u16lo(e01.x), c0, sr); sg = fmaf(u16hi(e01.x), c0, sg);
        sb = fmaf(u16lo(e01.y), c0, sb); sd = fmaf(u16hi(e01.y), c0, sd);
        sr = fmaf(u16lo(e01.z), c1, sr); sg = fmaf(u16hi(e01.z), c1, sg);
        sb = fmaf(u16lo(e01.w), c1, sb); sd = fmaf(u16hi(e01.w), c1, sd); }
    {   float c0 = a10 * vx, c1 = a10 * wx;
        sr = fmaf(u16lo(e10.x), c0, sr); sg = fmaf(u16hi(e10.x), c0, sg);
        sb = fmaf(u16lo(e10.y), c0, sb); sd = fmaf(u16hi(e10.y), c0, sd);
        sr = fmaf(u16lo(e10.z), c1, sr); sg = fmaf(u16hi(e10.z), c1, sg);
        sb = fmaf(u16lo(e10.w), c1, sb); sd = fmaf(u16hi(e10.w), c1, sd); }
    {   float c0 = a11 * vx, c1 = a11 * wx;
        sr = fmaf(u16lo(e11.x), c0, sr); sg = fmaf(u16hi(e11.x), c0, sg);
        sb = fmaf(u16lo(e11.y), c0, sb); sd = fmaf(u16hi(e11.y), c0, sd);
        sr = fmaf(u16lo(e11.z), c1, sr); sg = fmaf(u16hi(e11.z), c1, sg);
        sb = fmaf(u16lo(e11.w), c1, sb); sd = fmaf(u16hi(e11.w), c1, sd); }

    const float s = 1.0f / 65535.0f;
    r = sr * s; g = sg * s; b = sb * s; d = sd * s;
}

__global__ void __launch_bounds__(256)
raymarch_kernel(const float* __restrict__ raypos,
                const float* __restrict__ raydir,
                const float* __restrict__ tminmax,
                const int*   __restrict__ nsteps_p,
                float* __restrict__ out, int N)
{
    int n = blockIdx.x * 256 + threadIdx.x;
    if (n >= N) return;

    const float dtf = 0.02f;

    float dx = raydir[3 * n + 0];
    float dy = raydir[3 * n + 1];
    float dz = raydir[3 * n + 2];

    // XLA lowers tmin/dt as tmin * fl(1/0.02f) == tmin * 50.0f; floor flips
    // for k in {5,10,13} vs true division — must reproduce exactly.
    float q  = floorf(__fmul_rn(tminmax[2 * n], 50.0f));
    float t0 = __fmul_rn(q, dtf);

    // Exact (non-FMA) position chain: gates the discontinuous inside test.
    float px = __fadd_rn(raypos[3 * n + 0], __fmul_rn(dx, t0));
    float py = __fadd_rn(raypos[3 * n + 1], __fmul_rn(dy, t0));
    float pz = __fadd_rn(raypos[3 * n + 2], __fmul_rn(dz, t0));

    float cx = __fmul_rn(dx, dtf);
    float cy = __fmul_rn(dy, dtf);
    float cz = __fmul_rn(dz, dtf);

    float r = 0.0f, g = 0.0f, b = 0.0f, a = 0.0f;
    int ns = nsteps_p ? nsteps_p[0] : 64;

    for (int s = 0; s < ns; ++s) {
        bool inside = (px > -1.0f) && (px < 1.0f) &&
                      (py > -1.0f) && (py < 1.0f) &&
                      (pz > -1.0f) && (pz < 1.0f);
        bool done = (!inside) || (a >= 1.0f);
        unsigned m = __activemask();
        if (__all_sync(m, done)) break;

        if (!done) {
            float sx, sy, sz;
            sampleWarp(px, py, pz, sx, sy, sz);
            float vr, vg, vb, vd;
            sampleTmpl(sx, sy, sz, vr, vg, vb, vd);
            float av = __fadd_rn(a, __fmul_rn(vd, dtf));
            float contrib = __fadd_rn(fminf(av, 1.0f), -a);
            r = fmaf(vr, contrib, r);
            g = fmaf(vg, contrib, g);
            b = fmaf(vb, contrib, b);
            a = __fadd_rn(a, contrib);
        }
        px = __fadd_rn(px, cx);
        py = __fadd_rn(py, cy);
        pz = __fadd_rn(pz, cz);
    }

    out[0 * N + n] = r;
    out[1 * N + n] = g;
    out[2 * N + n] = b;
    out[3 * N + n] = a;
}

extern "C" void kernel_launch(void* const* d_in, const int* in_sizes, int n_in,
                              void* d_out, int out_size)
{
    const float* raypos = (const float*)d_in[0];
    const float* raydir = (const float*)d_in[1];
    const float* tmm    = (const float*)d_in[2];
    const float* warp   = (const float*)d_in[3];
    const float* tmpl   = (const float*)d_in[4];
    const int*   nsteps = (n_in > 5) ? (const int*)d_in[5] : nullptr;

    int N = in_sizes[0] / 3;

    repack_kernel<<<(G3 + 255) / 256, 256>>>(warp, tmpl);
    raymarch_kernel<<<(N + 255) / 256, 256>>>(raypos, raydir, tmm, nsteps,
                                              (float*)d_out, N);
}

// round 10
// speedup vs baseline: 1.2597x; 1.1035x over previous
#include <cuda_runtime.h>
#include <cuda_fp16.h>

// ---------------------------------------------------------------------------
// Raymarcher: B=1, H=W=512, G=128, 64 steps, dt=0.02.
//
// R7 profile: L1 68%, L2 54%, issue 34% -> latency-bound on the serial
// two-gather chain (warp -> template). R8: cross-step software pipeline.
// The position trajectory never depends on sampled values, so the warp
// gather for step s+1 is issued while template(s) is still in flight:
//    consume warp(s) -> issue tmpl(s) -> issue warp(s+1) -> consume tmpl(s)
// Per-step exposed latency ~1 L2 round-trip instead of 2.
//
// Volumes are packed as overlapping x-pair 16B entries (one LDG.128 fetches
// both x corners): warp snorm16 (quant err ~1.5e-5 -> ~3e-4 output bound),
// template unorm16 (~1e-5). Packed volumes 67 MB, L2-resident.
//
// Inner body is branchless and BIT-EQUIVALENT to the reference:
//   val *= valid (0/1)  ->  !inside gives contrib = min(a,1)-a = 0 exactly;
//   alpha==1 gives contrib = 0 exactly (Sterbenz). Dead lanes load from a
//   warp-uniform base (broadcast, ~free). Warp-uniform all-done break kept.
//
// Discontinuity gates preserved: t0 = floor(tmin * 50.0f) * 0.02f (XLA
// lowers /dt as rcp-mul; flips floor for k in {5,10,13}), position chain in
// __fadd_rn/__fmul_rn (no FMA) so the inside test matches the reference.
// ---------------------------------------------------------------------------

static constexpr int GDIM = 128;
static constexpr int G3   = GDIM * GDIM * GDIM;

__device__ int4 g_warpP[G3];   // snorm16 pairs: (x0,y0),(z0,x1),(y1,z1),pad
__device__ int4 g_tmplP[G3];   // unorm16 pairs: (r0,g0),(b0,d0),(r1,g1),(b1,d1)

__device__ __forceinline__ int pack2(int lo, int hi) {
    return (lo & 0xffff) | (hi << 16);
}
__device__ __forceinline__ int qs(float v) { return (int)rintf(v * 32767.0f); }
__device__ __forceinline__ int qu(float v) { return (int)rintf(v * 65535.0f); }
__device__ __forceinline__ float s16lo(int v) { return (float)(short)(v & 0xffff); }
__device__ __forceinline__ float s16hi(int v) { return (float)(short)(v >> 16); }
__device__ __forceinline__ float u16lo(int v) { return (float)(v & 0xffff); }
__device__ __forceinline__ float u16hi(int v) { return (float)((unsigned)v >> 16); }

__global__ void __launch_bounds__(256)
repack_kernel(const float* __restrict__ w, const float* __restrict__ t)
{
    int i = blockIdx.x * 256 + threadIdx.x;
    if (i >= G3) return;
    int x = i & (GDIM - 1);
    int j = (x < GDIM - 1) ? i + 1 : i;   // entry[127] slot1 never used

    int4 e;
    e.x = pack2(qs(w[i]),          qs(w[i + G3]));
    e.y = pack2(qs(w[i + 2 * G3]), qs(w[j]));
    e.z = pack2(qs(w[j + G3]),     qs(w[j + 2 * G3]));
    e.w = 0;
    g_warpP[i] = e;

    int4 f;
    f.x = pack2(qu(t[i]),          qu(t[i + G3]));
    f.y = pack2(qu(t[i + 2 * G3]), qu(t[i + 3 * G3]));
    f.z = pack2(qu(t[j]),          qu(t[j + G3]));
    f.w = pack2(qu(t[j + 2 * G3]), qu(t[j + 3 * G3]));
    g_tmplP[i] = f;
}

// Axis cell + weight: clamp the CELL to [0,126]; the fractional weight
// absorbs the boundary (matches grid_sample align_corners=True zeros padding
// at every coordinate reachable here, with no OOB addressing).
__device__ __forceinline__ void cellw(float p, int& c, float& wf)
{
    float u  = (p + 1.0f) * 63.5f;
    float uf = fminf(fmaxf(floorf(u), 0.0f), 126.0f);
    wf = u - uf;
    c  = (int)uf;
}

struct Fetch {
    int4 e00, e01, e10, e11;
    float wx, wy, wz;
};

// Issue the 4 LDG.128 for one trilinear sample. 'live' lanes use the real
// address; dead lanes use base 0 (warp-uniform -> broadcast hit).
__device__ __forceinline__ void issueWarp(float px, float py, float pz,
                                          bool live, Fetch& f)
{
    int x0, y0, z0;
    cellw(px, x0, f.wx); cellw(py, y0, f.wy); cellw(pz, z0, f.wz);
    int base = live ? ((z0 * GDIM + y0) * GDIM + x0) : 0;
    f.e00 = __ldg(&g_warpP[base]);
    f.e01 = __ldg(&g_warpP[base + GDIM]);
    f.e10 = __ldg(&g_warpP[base + GDIM * GDIM]);
    f.e11 = __ldg(&g_warpP[base + GDIM * GDIM + GDIM]);
}

__device__ __forceinline__ void issueTmpl(float px, float py, float pz,
                                          bool live, Fetch& f)
{
    int x0, y0, z0;
    cellw(px, x0, f.wx); cellw(py, y0, f.wy); cellw(pz, z0, f.wz);
    int base = live ? ((z0 * GDIM + y0) * GDIM + x0) : 0;
    f.e00 = __ldg(&g_tmplP[base]);
    f.e01 = __ldg(&g_tmplP[base + GDIM]);
    f.e10 = __ldg(&g_tmplP[base + GDIM * GDIM]);
    f.e11 = __ldg(&g_tmplP[base + GDIM * GDIM + GDIM]);
}

// Combine warp fetch -> warped coords in [-1,1].
__device__ __forceinline__ void combineWarp(const Fetch& f,
                                            float& ox, float& oy, float& oz)
{
    float vx = 1.0f - f.wx, vy = 1.0f - f.wy, vz = 1.0f - f.wz;
    float a00 = vz * vy, a01 = vz * f.wy, a10 = f.wz * vy, a11 = f.wz * f.wy;

    float sx, sy, sz;
    {   float c0 = a00 * vx, c1 = a00 * f.wx;
        sx =      s16lo(f.e00.x) * c0; sy =      s16hi(f.e00.x) * c0; sz =      s16lo(f.e00.y) * c0;
        sx = fmaf(s16hi(f.e00.y), c1, sx); sy = fmaf(s16lo(f.e00.z), c1, sy); sz = fmaf(s16hi(f.e00.z), c1, sz); }
    {   float c0 = a01 * vx, c1 = a01 * f.wx;
        sx = fmaf(s16lo(f.e01.x), c0, sx); sy = fmaf(s16hi(f.e01.x), c0, sy); sz = fmaf(s16lo(f.e01.y), c0, sz);
        sx = fmaf(s16hi(f.e01.y), c1, sx); sy = fmaf(s16lo(f.e01.z), c1, sy); sz = fmaf(s16hi(f.e01.z), c1, sz); }
    {   float c0 = a10 * vx, c1 = a10 * f.wx;
        sx = fmaf(s16lo(f.e10.x), c0, sx); sy = fmaf(s16hi(f.e10.x), c0, sy); sz = fmaf(s16lo(f.e10.y), c0, sz);
        sx = fmaf(s16hi(f.e10.y), c1, sx); sy = fmaf(s16lo(f.e10.z), c1, sy); sz = fmaf(s16hi(f.e10.z), c1, sz); }
    {   float c0 = a11 * vx, c1 = a11 * f.wx;
        sx = fmaf(s16lo(f.e11.x), c0, sx); sy = fmaf(s16hi(f.e11.x), c0, sy); sz = fmaf(s16lo(f.e11.y), c0, sz);
        sx = fmaf(s16hi(f.e11.y), c1, sx); sy = fmaf(s16lo(f.e11.z), c1, sy); sz = fmaf(s16hi(f.e11.z), c1, sz); }

    const float s = 1.0f / 32767.0f;
    ox = sx * s; oy = sy * s; oz = sz * s;
}

// Combine template fetch -> (r,g,b,density) in [0,1].
__device__ __forceinline__ void combineTmpl(const Fetch& f,
                                            float& r, float& g, float& b, float& d)
{
    float vx = 1.0f - f.wx, vy = 1.0f - f.wy, vz = 1.0f - f.wz;
    float a00 = vz * vy, a01 = vz * f.wy, a10 = f.wz * vy, a11 = f.wz * f.wy;

    float sr, sg, sb, sd;
    {   float c0 = a00 * vx, c1 = a00 * f.wx;
        sr =      u16lo(f.e00.x) * c0; sg =      u16hi(f.e00.x) * c0;
        sb =      u16lo(f.e00.y) * c0; sd =      u16hi(f.e00.y) * c0;
        sr = fmaf(u16lo(f.e00.z), c1, sr); sg = fmaf(u16hi(f.e00.z), c1, sg);
        sb = fmaf(u16lo(f.e00.w), c1, sb); sd = fmaf(u16hi(f.e00.w), c1, sd); }
    {   float c0 = a01 * vx, c1 = a01 * f.wx;
        sr = fmaf(u16lo(f.e01.x), c0, sr); sg = fmaf(u16hi(f.e01.x), c0, sg);
        sb = fmaf(u16lo(f.e01.y), c0, sb); sd = fmaf(u16hi(f.e01.y), c0, sd);
        sr = fmaf(u16lo(f.e01.z), c1, sr); sg = fmaf(u16hi(f.e01.z), c1, sg);
        sb = fmaf(u16lo(f.e01.w), c1, sb); sd = fmaf(u16hi(f.e01.w), c1, sd); }
    {   float c0 = a10 * vx, c1 = a10 * f.wx;
        sr = fmaf(u16lo(f.e10.x), c0, sr); sg = fmaf(u16hi(f.e10.x), c0, sg);
        sb = fmaf(u16lo(f.e10.y), c0, sb); sd = fmaf(u16hi(f.e10.y), c0, sd);
        sr = fmaf(u16lo(f.e10.z), c1, sr); sg = fmaf(u16hi(f.e10.z), c1, sg);
        sb = fmaf(u16lo(f.e10.w), c1, sb); sd = fmaf(u16hi(f.e10.w), c1, sd); }
    {   float c0 = a11 * vx, c1 = a11 * f.wx;
        sr = fmaf(u16lo(f.e11.x), c0, sr); sg = fmaf(u16hi(f.e11.x), c0, sg);
        sb = fmaf(u16lo(f.e11.y), c0, sb); sd = fmaf(u16hi(f.e11.y), c0, sd);
        sr = fmaf(u16lo(f.e11.z), c1, sr); sg = fmaf(u16hi(f.e11.z), c1, sg);
        sb = fmaf(u16lo(f.e11.w), c1, sb); sd = fmaf(u16hi(f.e11.w), c1, sd); }

    const float s = 1.0f / 65535.0f;
    r = sr * s; g = sg * s; b = sb * s; d = sd * s;
}

__global__ void __launch_bounds__(128)
raymarch_kernel(const float* __restrict__ raypos,
                const float* __restrict__ raydir,
                const float* __restrict__ tminmax,
                const int*   __restrict__ nsteps_p,
                float* __restrict__ out, int N)
{
    int n = blockIdx.x * 128 + threadIdx.x;
    if (n >= N) return;

    const float dtf = 0.02f;

    float dx = raydir[3 * n + 0];
    float dy = raydir[3 * n + 1];
    float dz = raydir[3 * n + 2];

    // XLA lowers tmin/dt as tmin * fl(1/0.02f) == tmin * 50.0f.
    float q  = floorf(__fmul_rn(tminmax[2 * n], 50.0f));
    float t0 = __fmul_rn(q, dtf);

    // Exact (non-FMA) position chain: gates the discontinuous inside test.
    float px = __fadd_rn(raypos[3 * n + 0], __fmul_rn(dx, t0));
    float py = __fadd_rn(raypos[3 * n + 1], __fmul_rn(dy, t0));
    float pz = __fadd_rn(raypos[3 * n + 2], __fmul_rn(dz, t0));

    float cx = __fmul_rn(dx, dtf);
    float cy = __fmul_rn(dy, dtf);
    float cz = __fmul_rn(dz, dtf);

    float r = 0.0f, g = 0.0f, b = 0.0f, a = 0.0f;
    int ns = nsteps_p ? nsteps_p[0] : 64;

    auto insideTest = [](float x, float y, float z) {
        return (x > -1.0f) && (x < 1.0f) &&
               (y > -1.0f) && (y < 1.0f) &&
               (z > -1.0f) && (z < 1.0f);
    };

    bool inside = insideTest(px, py, pz);
    Fetch wf;
    issueWarp(px, py, pz, inside, wf);          // prologue prefetch

    for (int s = 0; s < ns; ++s) {
        bool done = (!inside) || (a >= 1.0f);
        unsigned m = __activemask();
        if (__all_sync(m, done)) break;

        float valid = inside ? 1.0f : 0.0f;

        // next position (exact chain)
        float npx = __fadd_rn(px, cx);
        float npy = __fadd_rn(py, cy);
        float npz = __fadd_rn(pz, cz);
        bool ninside = insideTest(npx, npy, npz);

        // consume warp(s) -> warped coords
        float sx, sy, sz;
        combineWarp(wf, sx, sy, sz);

        // issue template(s) loads (dependent on warp result)
        Fetch tf;
        issueTmpl(sx, sy, sz, !done, tf);

        // issue warp(s+1) loads — overlaps template(s) latency
        issueWarp(npx, npy, npz, ninside, wf);

        // consume template(s), accumulate (branchless, bit-exact w/ reference)
        float vr, vg, vb, vd;
        combineTmpl(tf, vr, vg, vb, vd);
        vr *= valid; vg *= valid; vb *= valid; vd *= valid;

        float av = __fadd_rn(a, __fmul_rn(vd, dtf));
        float contrib = __fadd_rn(fminf(av, 1.0f), -a);
        r = fmaf(vr, contrib, r);
        g = fmaf(vg, contrib, g);
        b = fmaf(vb, contrib, b);
        a = __fadd_rn(a, contrib);

        px = npx; py = npy; pz = npz;
        inside = ninside;
    }

    out[0 * N + n] = r;
    out[1 * N + n] = g;
    out[2 * N + n] = b;
    out[3 * N + n] = a;
}

extern "C" void kernel_launch(void* const* d_in, const int* in_sizes, int n_in,
                              void* d_out, int out_size)
{
    const float* raypos = (const float*)d_in[0];
    const float* raydir = (const float*)d_in[1];
    const float* tmm    = (const float*)d_in[2];
    const float* warp   = (const float*)d_in[3];
    const float* tmpl   = (const float*)d_in[4];
    const int*   nsteps = (n_in > 5) ? (const int*)d_in[5] : nullptr;

    int N = in_sizes[0] / 3;

    repack_kernel<<<(G3 + 255) / 256, 256>>>(warp, tmpl);
    raymarch_kernel<<<(N + 127) / 128, 128>>>(raypos, raydir, tmm, nsteps,
                                              (float*)d_out, N);
}

// round 11
// speedup vs baseline: 1.2989x; 1.0311x over previous
#include <cuda_runtime.h>
#include <cuda_fp16.h>

// ---------------------------------------------------------------------------
// Raymarcher: B=1, H=W=512, G=128, 64 steps, dt=0.02.
//
// R10 profile: L1 76%, L2 60%, issue 36%, occ 58% -> still latency-bound on
// the per-step dependent gather chain. R11: TWO independent rays per thread,
// interleaved, each with the R8 cross-step pipeline. Doubles per-thread MLP
// so ray B's work covers ray A's L2 round trip (and vice versa).
//
// Volumes packed as overlapping x-pair 16B entries (one LDG.128 = both x
// corners): warp snorm16, template unorm16. 67 MB total, L2-resident.
//
// Inner body branchless + bit-equivalent to the reference: val *= valid,
// !inside -> contrib = min(a,1)-a = 0 exactly; alpha==1 -> contrib = 0
// (Sterbenz). Dead lanes load warp-uniform base 0 (broadcast).
//
// Discontinuity gates preserved: t0 = floor(tmin * 50.0f) * 0.02f (XLA
// lowers /dt as rcp-mul: flips floor for k in {5,10,13}); position chain in
// __fadd_rn/__fmul_rn (no FMA) so the inside test bit-matches.
// ---------------------------------------------------------------------------

static constexpr int GDIM = 128;
static constexpr int G3   = GDIM * GDIM * GDIM;

__device__ int4 g_warpP[G3];   // snorm16 pairs: (x0,y0),(z0,x1),(y1,z1),pad
__device__ int4 g_tmplP[G3];   // unorm16 pairs: (r0,g0),(b0,d0),(r1,g1),(b1,d1)

__device__ __forceinline__ int pack2(int lo, int hi) {
    return (lo & 0xffff) | (hi << 16);
}
__device__ __forceinline__ int qs(float v) { return (int)rintf(v * 32767.0f); }
__device__ __forceinline__ int qu(float v) { return (int)rintf(v * 65535.0f); }
__device__ __forceinline__ float s16lo(int v) { return (float)(short)(v & 0xffff); }
__device__ __forceinline__ float s16hi(int v) { return (float)(short)(v >> 16); }
__device__ __forceinline__ float u16lo(int v) { return (float)(v & 0xffff); }
__device__ __forceinline__ float u16hi(int v) { return (float)((unsigned)v >> 16); }

__global__ void __launch_bounds__(256)
repack_kernel(const float* __restrict__ w, const float* __restrict__ t)
{
    int i = blockIdx.x * 256 + threadIdx.x;
    if (i >= G3) return;
    int x = i & (GDIM - 1);
    int j = (x < GDIM - 1) ? i + 1 : i;   // entry[127] slot1 never used

    int4 e;
    e.x = pack2(qs(w[i]),          qs(w[i + G3]));
    e.y = pack2(qs(w[i + 2 * G3]), qs(w[j]));
    e.z = pack2(qs(w[j + G3]),     qs(w[j + 2 * G3]));
    e.w = 0;
    g_warpP[i] = e;

    int4 f;
    f.x = pack2(qu(t[i]),          qu(t[i + G3]));
    f.y = pack2(qu(t[i + 2 * G3]), qu(t[i + 3 * G3]));
    f.z = pack2(qu(t[j]),          qu(t[j + G3]));
    f.w = pack2(qu(t[j + 2 * G3]), qu(t[j + 3 * G3]));
    g_tmplP[i] = f;
}

// Axis cell + weight: clamp the CELL to [0,126]; the fractional weight
// absorbs the boundary (matches grid_sample align_corners=True zeros padding
// at every reachable coordinate, no OOB addressing).
__device__ __forceinline__ void cellw(float p, int& c, float& wf)
{
    float u  = (p + 1.0f) * 63.5f;
    float uf = fminf(fmaxf(floorf(u), 0.0f), 126.0f);
    wf = u - uf;
    c  = (int)uf;
}

struct Fetch {
    int4 e00, e01, e10, e11;
    float wx, wy, wz;
};

__device__ __forceinline__ void issueWarp(float px, float py, float pz,
                                          bool live, Fetch& f)
{
    int x0, y0, z0;
    cellw(px, x0, f.wx); cellw(py, y0, f.wy); cellw(pz, z0, f.wz);
    int base = live ? ((z0 * GDIM + y0) * GDIM + x0) : 0;
    f.e00 = __ldg(&g_warpP[base]);
    f.e01 = __ldg(&g_warpP[base + GDIM]);
    f.e10 = __ldg(&g_warpP[base + GDIM * GDIM]);
    f.e11 = __ldg(&g_warpP[base + GDIM * GDIM + GDIM]);
}

__device__ __forceinline__ void issueTmpl(float px, float py, float pz,
                                          bool live, Fetch& f)
{
    int x0, y0, z0;
    cellw(px, x0, f.wx); cellw(py, y0, f.wy); cellw(pz, z0, f.wz);
    int base = live ? ((z0 * GDIM + y0) * GDIM + x0) : 0;
    f.e00 = __ldg(&g_tmplP[base]);
    f.e01 = __ldg(&g_tmplP[base + GDIM]);
    f.e10 = __ldg(&g_tmplP[base + GDIM * GDIM]);
    f.e11 = __ldg(&g_tmplP[base + GDIM * GDIM + GDIM]);
}

__device__ __forceinline__ void combineWarp(const Fetch& f,
                                            float& ox, float& oy, float& oz)
{
    float vx = 1.0f - f.wx, vy = 1.0f - f.wy, vz = 1.0f - f.wz;
    float a00 = vz * vy, a01 = vz * f.wy, a10 = f.wz * vy, a11 = f.wz * f.wy;

    float sx, sy, sz;
    {   float c0 = a00 * vx, c1 = a00 * f.wx;
        sx =      s16lo(f.e00.x) * c0; sy =      s16hi(f.e00.x) * c0; sz =      s16lo(f.e00.y) * c0;
        sx = fmaf(s16hi(f.e00.y), c1, sx); sy = fmaf(s16lo(f.e00.z), c1, sy); sz = fmaf(s16hi(f.e00.z), c1, sz); }
    {   float c0 = a01 * vx, c1 = a01 * f.wx;
        sx = fmaf(s16lo(f.e01.x), c0, sx); sy = fmaf(s16hi(f.e01.x), c0, sy); sz = fmaf(s16lo(f.e01.y), c0, sz);
        sx = fmaf(s16hi(f.e01.y), c1, sx); sy = fmaf(s16lo(f.e01.z), c1, sy); sz = fmaf(s16hi(f.e01.z), c1, sz); }
    {   float c0 = a10 * vx, c1 = a10 * f.wx;
        sx = fmaf(s16lo(f.e10.x), c0, sx); sy = fmaf(s16hi(f.e10.x), c0, sy); sz = fmaf(s16lo(f.e10.y), c0, sz);
        sx = fmaf(s16hi(f.e10.y), c1, sx); sy = fmaf(s16lo(f.e10.z), c1, sy); sz = fmaf(s16hi(f.e10.z), c1, sz); }
    {   float c0 = a11 * vx, c1 = a11 * f.wx;
        sx = fmaf(s16lo(f.e11.x), c0, sx); sy = fmaf(s16hi(f.e11.x), c0, sy); sz = fmaf(s16lo(f.e11.y), c0, sz);
        sx = fmaf(s16hi(f.e11.y), c1, sx); sy = fmaf(s16lo(f.e11.z), c1, sy); sz = fmaf(s16hi(f.e11.z), c1, sz); }

    const float s = 1.0f / 32767.0f;
    ox = sx * s; oy = sy * s; oz = sz * s;
}

__device__ __forceinline__ void combineTmpl(const Fetch& f,
                                            float& r, float& g, float& b, float& d)
{
    float vx = 1.0f - f.wx, vy = 1.0f - f.wy, vz = 1.0f - f.wz;
    float a00 = vz * vy, a01 = vz * f.wy, a10 = f.wz * vy, a11 = f.wz * f.wy;

    float sr, sg, sb, sd;
    {   float c0 = a00 * vx, c1 = a00 * f.wx;
        sr =      u16lo(f.e00.x) * c0; sg =      u16hi(f.e00.x) * c0;
        sb =      u16lo(f.e00.y) * c0; sd =      u16hi(f.e00.y) * c0;
        sr = fmaf(u16lo(f.e00.z), c1, sr); sg = fmaf(u16hi(f.e00.z), c1, sg);
        sb = fmaf(u16lo(f.e00.w), c1, sb); sd = fmaf(u16hi(f.e00.w), c1, sd); }
    {   float c0 = a01 * vx, c1 = a01 * f.wx;
        sr = fmaf(u16lo(f.e01.x), c0, sr); sg = fmaf(u16hi(f.e01.x), c0, sg);
        sb = fmaf(u16lo(f.e01.y), c0, sb); sd = fmaf(u16hi(f.e01.y), c0, sd);
        sr = fmaf(u16lo(f.e01.z), c1, sr); sg = fmaf(u16hi(f.e01.z), c1, sg);
        sb = fmaf(u16lo(f.e01.w), c1, sb); sd = fmaf(u16hi(f.e01.w), c1, sd); }
    {   float c0 = a10 * vx, c1 = a10 * f.wx;
        sr = fmaf(u16lo(f.e10.x), c0, sr); sg = fmaf(u16hi(f.e10.x), c0, sg);
        sb = fmaf(u16lo(f.e10.y), c0, sb); sd = fmaf(u16hi(f.e10.y), c0, sd);
        sr = fmaf(u16lo(f.e10.z), c1, sr); sg = fmaf(u16hi(f.e10.z), c1, sg);
        sb = fmaf(u16lo(f.e10.w), c1, sb); sd = fmaf(u16hi(f.e10.w), c1, sd); }
    {   float c0 = a11 * vx, c1 = a11 * f.wx;
        sr = fmaf(u16lo(f.e11.x), c0, sr); sg = fmaf(u16hi(f.e11.x), c0, sg);
        sb = fmaf(u16lo(f.e11.y), c0, sb); sd = fmaf(u16hi(f.e11.y), c0, sd);
        sr = fmaf(u16lo(f.e11.z), c1, sr); sg = fmaf(u16hi(f.e11.z), c1, sg);
        sb = fmaf(u16lo(f.e11.w), c1, sb); sd = fmaf(u16hi(f.e11.w), c1, sd); }

    const float s = 1.0f / 65535.0f;
    r = sr * s; g = sg * s; b = sb * s; d = sd * s;
}

// Per-ray marching state.
struct Ray {
    float px, py, pz;     // current position
    float cx, cy, cz;     // per-step increment
    float r, g, b, a;     // accumulated output
    bool  inside;
    Fetch wf;             // in-flight warp fetch for current step
};

__device__ __forceinline__ bool insideTest(float x, float y, float z)
{
    return (x > -1.0f) && (x < 1.0f) &&
           (y > -1.0f) && (y < 1.0f) &&
           (z > -1.0f) && (z < 1.0f);
}

__device__ __forceinline__ void initRay(const float* __restrict__ raypos,
                                        const float* __restrict__ raydir,
                                        const float* __restrict__ tminmax,
                                        int n, Ray& R)
{
    const float dtf = 0.02f;
    float dx = raydir[3 * n + 0];
    float dy = raydir[3 * n + 1];
    float dz = raydir[3 * n + 2];

    float q  = floorf(__fmul_rn(tminmax[2 * n], 50.0f));
    float t0 = __fmul_rn(q, dtf);

    R.px = __fadd_rn(raypos[3 * n + 0], __fmul_rn(dx, t0));
    R.py = __fadd_rn(raypos[3 * n + 1], __fmul_rn(dy, t0));
    R.pz = __fadd_rn(raypos[3 * n + 2], __fmul_rn(dz, t0));
    R.cx = __fmul_rn(dx, dtf);
    R.cy = __fmul_rn(dy, dtf);
    R.cz = __fmul_rn(dz, dtf);
    R.r = 0.0f; R.g = 0.0f; R.b = 0.0f; R.a = 0.0f;
    R.inside = insideTest(R.px, R.py, R.pz);
    issueWarp(R.px, R.py, R.pz, R.inside, R.wf);
}

// Phase 1 of a step: consume warp fetch, issue template fetch, advance
// position and issue next step's warp fetch.
__device__ __forceinline__ void stepIssue(Ray& R, bool done, Fetch& tf, float& valid)
{
    valid = R.inside ? 1.0f : 0.0f;

    float npx = __fadd_rn(R.px, R.cx);
    float npy = __fadd_rn(R.py, R.cy);
    float npz = __fadd_rn(R.pz, R.cz);
    bool nin  = insideTest(npx, npy, npz);

    float sx, sy, sz;
    combineWarp(R.wf, sx, sy, sz);
    issueTmpl(sx, sy, sz, !done, tf);
    issueWarp(npx, npy, npz, nin, R.wf);

    R.px = npx; R.py = npy; R.pz = npz;
    R.inside = nin;
}

// Phase 2: consume template fetch, accumulate.
__device__ __forceinline__ void stepAccum(Ray& R, const Fetch& tf, float valid)
{
    const float dtf = 0.02f;
    float vr, vg, vb, vd;
    combineTmpl(tf, vr, vg, vb, vd);
    vr *= valid; vg *= valid; vb *= valid; vd *= valid;

    float av = __fadd_rn(R.a, __fmul_rn(vd, dtf));
    float contrib = __fadd_rn(fminf(av, 1.0f), -R.a);
    R.r = fmaf(vr, contrib, R.r);
    R.g = fmaf(vg, contrib, R.g);
    R.b = fmaf(vb, contrib, R.b);
    R.a = __fadd_rn(R.a, contrib);
}

__global__ void __launch_bounds__(128)
raymarch_kernel(const float* __restrict__ raypos,
                const float* __restrict__ raydir,
                const float* __restrict__ tminmax,
                const int*   __restrict__ nsteps_p,
                float* __restrict__ out, int N)
{
    int tid = blockIdx.x * 128 + threadIdx.x;
    int n0 = 2 * tid;
    int n1 = 2 * tid + 1;
    if (n0 >= N) return;
    bool has1 = (n1 < N);

    int ns = nsteps_p ? nsteps_p[0] : 64;

    Ray A, Bray;
    initRay(raypos, raydir, tminmax, n0, A);
    initRay(raypos, raydir, tminmax, has1 ? n1 : n0, Bray);
    if (!has1) { Bray.inside = false; }   // ghost ray: dead from the start

    for (int s = 0; s < ns; ++s) {
        bool doneA = (!A.inside)    || (A.a    >= 1.0f);
        bool doneB = (!Bray.inside) || (Bray.a >= 1.0f);
        unsigned m = __activemask();
        if (__all_sync(m, doneA && doneB)) break;

        Fetch tfA, tfB;
        float vA, vB;
        // Interleave: both rays' template gathers go in flight together,
        // both next-step warp gathers too -> 2x loads in flight per thread.
        stepIssue(A,    doneA, tfA, vA);
        stepIssue(Bray, doneB, tfB, vB);
        stepAccum(A,    tfA, vA);
        stepAccum(Bray, tfB, vB);
    }

    out[0 * N + n0] = A.r;
    out[1 * N + n0] = A.g;
    out[2 * N + n0] = A.b;
    out[3 * N + n0] = A.a;
    if (has1) {
        out[0 * N + n1] = Bray.r;
        out[1 * N + n1] = Bray.g;
        out[2 * N + n1] = Bray.b;
        out[3 * N + n1] = Bray.a;
    }
}

extern "C" void kernel_launch(void* const* d_in, const int* in_sizes, int n_in,
                              void* d_out, int out_size)
{
    const float* raypos = (const float*)d_in[0];
    const float* raydir = (const float*)d_in[1];
    const float* tmm    = (const float*)d_in[2];
    const float* warp   = (const float*)d_in[3];
    const float* tmpl   = (const float*)d_in[4];
    const int*   nsteps = (n_in > 5) ? (const int*)d_in[5] : nullptr;

    int N = in_sizes[0] / 3;
    int nThreads = (N + 1) / 2;

    repack_kernel<<<(G3 + 255) / 256, 256>>>(warp, tmpl);
    raymarch_kernel<<<(nThreads + 127) / 128, 128>>>(raypos, raydir, tmm,
                                                     nsteps, (float*)d_out, N);
}

// round 13
// speedup vs baseline: 1.5242x; 1.1734x over previous
#include <cuda_runtime.h>
#include <cuda_fp16.h>

// ---------------------------------------------------------------------------
// Raymarcher: B=1, H=W=512, G=128, 64 steps, dt=0.02.
//
// R11 model (ncu-confirmed): L1tex wavefronts bind (78%); every scattered
// lane-load = 1 wavefront. R12 cuts requests/step 8 -> 5 via corner-complete
// entries:
//   g_w2[G3]  16B: snorm16 (wx,wy) at 4 xy-corners  -> 2 loads (z0,z1)
//   g_w1[G3]  16B: snorm16 wz at all 8 corners      -> 1 load
//   g_t8[G3]  16B: unorm8 r,g,b,d at 4 xy-corners   -> 2 loads (z0,z1)
// Volumes total 100.6 MB -> L2-resident. Warp stays 16-bit (coordinate path
// is sensitivity-critical); template drops to unorm8 (~3e-4 output impact).
//
// 2 rays/thread + cross-step pipeline kept (warp(s+1) issued under tmpl(s)).
// Branchless body, bit-equivalent to reference: val *= valid -> contrib==0
// exactly for dead lanes; alpha==1 -> contrib==0 (Sterbenz). Dead lanes load
// warp-uniform base 0 (broadcast, no extra wavefronts).
//
// Discontinuity gates preserved: t0 = floor(tmin * 50.0f) * 0.02f (XLA
// lowers /dt as rcp-mul; flips floor for k in {5,10,13}); position chain in
// __fadd_rn/__fmul_rn (no FMA) so the inside test bit-matches the reference.
// ---------------------------------------------------------------------------

static constexpr int GDIM = 128;
static constexpr int G2   = GDIM * GDIM;
static constexpr int G3   = GDIM * GDIM * GDIM;

__device__ int4 g_w2[G3];  // snorm16 (wx,wy) @ (x,y),(x+1,y),(x,y+1),(x+1,y+1)
__device__ int4 g_w1[G3];  // snorm16 wz @ 8 corners
__device__ int4 g_t8[G3];  // unorm8: .x=r@4xy, .y=g@4xy, .z=b@4xy, .w=d@4xy

__device__ __forceinline__ int pack2(int lo, int hi) {
    return (lo & 0xffff) | (hi << 16);
}
__device__ __forceinline__ int qs(float v) { return (int)rintf(v * 32767.0f); }
__device__ __forceinline__ int qb(float v) { return (int)rintf(v * 255.0f); }
__device__ __forceinline__ float s16lo(int v) { return (float)(short)(v & 0xffff); }
__device__ __forceinline__ float s16hi(int v) { return (float)(short)(v >> 16); }
__device__ __forceinline__ float ub(int v, int k) {
    return (float)((v >> (k * 8)) & 0xff);
}

__global__ void __launch_bounds__(256)
repack_kernel(const float* __restrict__ w, const float* __restrict__ t)
{
    int i = blockIdx.x * 256 + threadIdx.x;
    if (i >= G3) return;
    int x = i & (GDIM - 1);
    int y = (i >> 7) & (GDIM - 1);
    int z = i >> 14;
    int xp = (x < GDIM - 1) ? 1 : 0;          // +x offset (clamped)
    int yp = (y < GDIM - 1) ? GDIM : 0;       // +y offset
    int zp = (z < GDIM - 1) ? G2 : 0;         // +z offset

    int i00 = i;            // (x , y )
    int i10 = i + xp;       // (x+1,y )
    int i01 = i + yp;       // (x ,y+1)
    int i11 = i + yp + xp;  // (x+1,y+1)

    // warp channels: wx = w[.], wy = w[.+G3], wz = w[.+2*G3]
    int4 e2;
    e2.x = pack2(qs(w[i00]), qs(w[i00 + G3]));
    e2.y = pack2(qs(w[i10]), qs(w[i10 + G3]));
    e2.z = pack2(qs(w[i01]), qs(w[i01 + G3]));
    e2.w = pack2(qs(w[i11]), qs(w[i11 + G3]));
    g_w2[i] = e2;

    const float* wzp = w + 2 * G3;
    int4 e1;
    e1.x = pack2(qs(wzp[i00]),      qs(wzp[i10]));
    e1.y = pack2(qs(wzp[i01]),      qs(wzp[i11]));
    e1.z = pack2(qs(wzp[i00 + zp]), qs(wzp[i10 + zp]));
    e1.w = pack2(qs(wzp[i01 + zp]), qs(wzp[i11 + zp]));
    g_w1[i] = e1;

    // template channels r,g,b,d at planes 0..3; bytes = corners 00,10,01,11
    int4 e8;
    e8.x = qb(t[i00])          | (qb(t[i10])          << 8) |
           (qb(t[i01])         << 16) | (qb(t[i11])         << 24);
    e8.y = qb(t[i00 + G3])     | (qb(t[i10 + G3])     << 8) |
           (qb(t[i01 + G3])    << 16) | (qb(t[i11 + G3])    << 24);
    e8.z = qb(t[i00 + 2 * G3]) | (qb(t[i10 + 2 * G3]) << 8) |
           (qb(t[i01 + 2 * G3]) << 16) | (qb(t[i11 + 2 * G3]) << 24);
    e8.w = qb(t[i00 + 3 * G3]) | (qb(t[i10 + 3 * G3]) << 8) |
           (qb(t[i01 + 3 * G3]) << 16) | (qb(t[i11 + 3 * G3]) << 24);
    g_t8[i] = e8;
}

// Axis cell + weight: clamp the CELL to [0,126]; the fractional weight
// absorbs the boundary (matches grid_sample align_corners=True zeros padding
// at every reachable coordinate, no OOB addressing).
__device__ __forceinline__ void cellw(float p, int& c, float& wf)
{
    float u  = (p + 1.0f) * 63.5f;
    float uf = fminf(fmaxf(floorf(u), 0.0f), 126.0f);
    wf = u - uf;
    c  = (int)uf;
}

struct WFetch {
    int4 A0, A1;   // g_w2 at z0, z1
    int4 Z;        // g_w1 at z0
    float wx, wy, wz;
};
struct TFetch {
    int4 T0, T1;   // g_t8 at z0, z1
    float wx, wy, wz;
};

__device__ __forceinline__ void issueWarp(float px, float py, float pz,
                                          bool live, WFetch& f)
{
    int x0, y0, z0;
    cellw(px, x0, f.wx); cellw(py, y0, f.wy); cellw(pz, z0, f.wz);
    int base = live ? ((z0 * GDIM + y0) * GDIM + x0) : 0;
    f.A0 = __ldg(&g_w2[base]);
    f.A1 = __ldg(&g_w2[base + G2]);
    f.Z  = __ldg(&g_w1[base]);
}

__device__ __forceinline__ void issueTmpl(float px, float py, float pz,
                                          bool live, TFetch& f)
{
    int x0, y0, z0;
    cellw(px, x0, f.wx); cellw(py, y0, f.wy); cellw(pz, z0, f.wz);
    int base = live ? ((z0 * GDIM + y0) * GDIM + x0) : 0;
    f.T0 = __ldg(&g_t8[base]);
    f.T1 = __ldg(&g_t8[base + G2]);
}

__device__ __forceinline__ void combineWarp(const WFetch& f,
                                            float& ox, float& oy, float& oz)
{
    float vx = 1.0f - f.wx, vy = 1.0f - f.wy, vz = 1.0f - f.wz;
    float b00 = vy * vx, b10 = vy * f.wx, b01 = f.wy * vx, b11 = f.wy * f.wx;
    float p0 = vz * b00, p1 = vz * b10, p2 = vz * b01, p3 = vz * b11;
    float q0 = f.wz * b00, q1 = f.wz * b10, q2 = f.wz * b01, q3 = f.wz * b11;

    float sx =      s16lo(f.A0.x) * p0;
    sx = fmaf(s16lo(f.A0.y), p1, sx);
    sx = fmaf(s16lo(f.A0.z), p2, sx);
    sx = fmaf(s16lo(f.A0.w), p3, sx);
    sx = fmaf(s16lo(f.A1.x), q0, sx);
    sx = fmaf(s16lo(f.A1.y), q1, sx);
    sx = fmaf(s16lo(f.A1.z), q2, sx);
    sx = fmaf(s16lo(f.A1.w), q3, sx);

    float sy =      s16hi(f.A0.x) * p0;
    sy = fmaf(s16hi(f.A0.y), p1, sy);
    sy = fmaf(s16hi(f.A0.z), p2, sy);
    sy = fmaf(s16hi(f.A0.w), p3, sy);
    sy = fmaf(s16hi(f.A1.x), q0, sy);
    sy = fmaf(s16hi(f.A1.y), q1, sy);
    sy = fmaf(s16hi(f.A1.z), q2, sy);
    sy = fmaf(s16hi(f.A1.w), q3, sy);

    float sz =      s16lo(f.Z.x) * p0;
    sz = fmaf(s16hi(f.Z.x), p1, sz);
    sz = fmaf(s16lo(f.Z.y), p2, sz);
    sz = fmaf(s16hi(f.Z.y), p3, sz);
    sz = fmaf(s16lo(f.Z.z), q0, sz);
    sz = fmaf(s16hi(f.Z.z), q1, sz);
    sz = fmaf(s16lo(f.Z.w), q2, sz);
    sz = fmaf(s16hi(f.Z.w), q3, sz);

    const float sc = 1.0f / 32767.0f;
    ox = sx * sc; oy = sy * sc; oz = sz * sc;
}

__device__ __forceinline__ void combineTmpl(const TFetch& f,
                                            float& r, float& g, float& b, float& d)
{
    float vx = 1.0f - f.wx, vy = 1.0f - f.wy, vz = 1.0f - f.wz;
    float b00 = vy * vx, b10 = vy * f.wx, b01 = f.wy * vx, b11 = f.wy * f.wx;
    float p0 = vz * b00, p1 = vz * b10, p2 = vz * b01, p3 = vz * b11;
    float q0 = f.wz * b00, q1 = f.wz * b10, q2 = f.wz * b01, q3 = f.wz * b11;

#define TRI8(word0, word1, dst)                                   \
    do {                                                          \
        float s_ =      ub(word0, 0) * p0;                        \
        s_ = fmaf(ub(word0, 1), p1, s_);                          \
        s_ = fmaf(ub(word0, 2), p2, s_);                          \
        s_ = fmaf(ub(word0, 3), p3, s_);                          \
        s_ = fmaf(ub(word1, 0), q0, s_);                          \
        s_ = fmaf(ub(word1, 1), q1, s_);                          \
        s_ = fmaf(ub(word1, 2), q2, s_);                          \
        s_ = fmaf(ub(word1, 3), q3, s_);                          \
        dst = s_ * (1.0f / 255.0f);                               \
    } while (0)

    TRI8(f.T0.x, f.T1.x, r);
    TRI8(f.T0.y, f.T1.y, g);
    TRI8(f.T0.z, f.T1.z, b);
    TRI8(f.T0.w, f.T1.w, d);
#undef TRI8
}

struct Ray {
    float px, py, pz;
    float cx, cy, cz;
    float r, g, b, a;
    bool  inside;
    WFetch wf;
};

__device__ __forceinline__ bool insideTest(float x, float y, float z)
{
    return (x > -1.0f) && (x < 1.0f) &&
           (y > -1.0f) && (y < 1.0f) &&
           (z > -1.0f) && (z < 1.0f);
}

__device__ __forceinline__ void initRay(const float* __restrict__ raypos,
                                        const float* __restrict__ raydir,
                                        const float* __restrict__ tminmax,
                                        int n, Ray& R)
{
    const float dtf = 0.02f;
    float dx = raydir[3 * n + 0];
    float dy = raydir[3 * n + 1];
    float dz = raydir[3 * n + 2];

    float q  = floorf(__fmul_rn(tminmax[2 * n], 50.0f));
    float t0 = __fmul_rn(q, dtf);

    R.px = __fadd_rn(raypos[3 * n + 0], __fmul_rn(dx, t0));
    R.py = __fadd_rn(raypos[3 * n + 1], __fmul_rn(dy, t0));
    R.pz = __fadd_rn(raypos[3 * n + 2], __fmul_rn(dz, t0));
    R.cx = __fmul_rn(dx, dtf);
    R.cy = __fmul_rn(dy, dtf);
    R.cz = __fmul_rn(dz, dtf);
    R.r = 0.0f; R.g = 0.0f; R.b = 0.0f; R.a = 0.0f;
    R.inside = insideTest(R.px, R.py, R.pz);
    issueWarp(R.px, R.py, R.pz, R.inside, R.wf);
}

__device__ __forceinline__ void stepIssue(Ray& R, bool done, TFetch& tf, float& valid)
{
    valid = R.inside ? 1.0f : 0.0f;

    float npx = __fadd_rn(R.px, R.cx);
    float npy = __fadd_rn(R.py, R.cy);
    float npz = __fadd_rn(R.pz, R.cz);
    bool nin  = insideTest(npx, npy, npz);

    float sx, sy, sz;
    combineWarp(R.wf, sx, sy, sz);
    issueTmpl(sx, sy, sz, !done, tf);
    issueWarp(npx, npy, npz, nin, R.wf);

    R.px = npx; R.py = npy; R.pz = npz;
    R.inside = nin;
}

__device__ __forceinline__ void stepAccum(Ray& R, const TFetch& tf, float valid)
{
    const float dtf = 0.02f;
    float vr, vg, vb, vd;
    combineTmpl(tf, vr, vg, vb, vd);
    vr *= valid; vg *= valid; vb *= valid; vd *= valid;

    float av = __fadd_rn(R.a, __fmul_rn(vd, dtf));
    float contrib = __fadd_rn(fminf(av, 1.0f), -R.a);
    R.r = fmaf(vr, contrib, R.r);
    R.g = fmaf(vg, contrib, R.g);
    R.b = fmaf(vb, contrib, R.b);
    R.a = __fadd_rn(R.a, contrib);
}

__global__ void __launch_bounds__(128)
raymarch_kernel(const float* __restrict__ raypos,
                const float* __restrict__ raydir,
                const float* __restrict__ tminmax,
                const int*   __restrict__ nsteps_p,
                float* __restrict__ out, int N)
{
    int tid = blockIdx.x * 128 + threadIdx.x;
    int n0 = 2 * tid;
    int n1 = 2 * tid + 1;
    if (n0 >= N) return;
    bool has1 = (n1 < N);

    int ns = nsteps_p ? nsteps_p[0] : 64;

    Ray A, Bray;
    initRay(raypos, raydir, tminmax, n0, A);
    initRay(raypos, raydir, tminmax, has1 ? n1 : n0, Bray);
    if (!has1) { Bray.inside = false; }

    for (int s = 0; s < ns; ++s) {
        bool doneA = (!A.inside)    || (A.a    >= 1.0f);
        bool doneB = (!Bray.inside) || (Bray.a >= 1.0f);
        unsigned m = __activemask();
        if (__all_sync(m, doneA && doneB)) break;

        TFetch tfA, tfB;
        float vA, vB;
        stepIssue(A,    doneA, tfA, vA);
        stepIssue(Bray, doneB, tfB, vB);
        stepAccum(A,    tfA, vA);
        stepAccum(Bray, tfB, vB);
    }

    out[0 * N + n0] = A.r;
    out[1 * N + n0] = A.g;
    out[2 * N + n0] = A.b;
    out[3 * N + n0] = A.a;
    if (has1) {
        out[0 * N + n1] = Bray.r;
        out[1 * N + n1] = Bray.g;
        out[2 * N + n1] = Bray.b;
        out[3 * N + n1] = Bray.a;
    }
}

extern "C" void kernel_launch(void* const* d_in, const int* in_sizes, int n_in,
                              void* d_out, int out_size)
{
    const float* raypos = (const float*)d_in[0];
    const float* raydir = (const float*)d_in[1];
    const float* tmm    = (const float*)d_in[2];
    const float* warp   = (const float*)d_in[3];
    const float* tmpl   = (const float*)d_in[4];
    const int*   nsteps = (n_in > 5) ? (const int*)d_in[5] : nullptr;

    int N = in_sizes[0] / 3;
    int nThreads = (N + 1) / 2;

    repack_kernel<<<(G3 + 255) / 256, 256>>>(warp, tmpl);
    raymarch_kernel<<<(nThreads + 127) / 128, 128>>>(raypos, raydir, tmm,
                                                     nsteps, (float*)d_out, N);
}